// round 9
// baseline (speedup 1.0000x reference)
#include <cuda_runtime.h>
#include <cstdint>

// Shapes fixed by the reference:
//   x: [N, 128] f32, adj_row/adj_col: [E] int32-or-int64 (runtime detect),
//   adj_val: [E] f32, W: [128, 64] f32, b: [64] f32 -> out: [N, 64] f32
#define MAX_NODES 131072
#define E_CAP     1700000
#define F_IN  128
#define F_OUT 64
#define SCAN_CHUNK 1024
#define SCAN_MAXBLK 128

#define ROWS_PER_BLOCK 64       // gemm tile rows (103 KB smem -> 2 CTAs/SM)
#define XS_STRIDE 132           // xs row stride (floats) — conflict-free A frags
#define WS_STRIDE 68            // W smem stride (floats)
#define GEMM_SMEM_BYTES ((2 * F_IN * WS_STRIDE + ROWS_PER_BLOCK * XS_STRIDE) * 4)

// ---- static device scratch (no cudaMalloc allowed) ----
__device__ __align__(16) float g_xw[(size_t)MAX_NODES * F_OUT];
__device__ long long g_packed[E_CAP];      // lo32=col, hi32=val bits
__device__ int g_cnt[MAX_NODES];
__device__ int g_incl[MAX_NODES];
__device__ int g_blocktot[SCAN_MAXBLK];
__device__ int g_row_ptr[MAX_NODES + 1];
__device__ int g_cursor[MAX_NODES];
__device__ int g_idx64;

__device__ __forceinline__ int load_idx(const void* p, int e)
{
    return g_idx64 ? (int)((const long long*)p)[e] : ((const int*)p)[e];
}

__device__ __forceinline__ unsigned f2tf32(float f)
{
    unsigned u;
    asm("cvt.rna.tf32.f32 %0, %1;" : "=r"(u) : "f"(f));
    return u;
}

__device__ __forceinline__ void mma_tf32(float* d, const unsigned* a,
                                         unsigned b0, unsigned b1)
{
    asm volatile(
        "mma.sync.aligned.m16n8k8.row.col.f32.tf32.tf32.f32 "
        "{%0,%1,%2,%3}, {%4,%5,%6,%7}, {%8,%9}, {%0,%1,%2,%3};"
        : "+f"(d[0]), "+f"(d[1]), "+f"(d[2]), "+f"(d[3])
        : "r"(a[0]), "r"(a[1]), "r"(a[2]), "r"(a[3]), "r"(b0), "r"(b1));
}

// ---------------------------------------------------------------------------
// Kernel 1: prep = zero g_cnt + index-dtype detect (block 0).
// ---------------------------------------------------------------------------
__global__ __launch_bounds__(256) void prep_kernel(
    const int* __restrict__ row_raw, int n_edges, int n_nodes)
{
    int i = blockIdx.x * blockDim.x + threadIdx.x;
    if (i < n_nodes) g_cnt[i] = 0;

    if (blockIdx.x == 0) {
        __shared__ int any_nonzero;
        int t = threadIdx.x;
        if (t == 0) any_nonzero = 0;
        __syncthreads();
        int limit = n_edges < 64 ? n_edges : 64;
        if (t < limit && row_raw[2 * t + 1] != 0)
            atomicOr(&any_nonzero, 1);
        __syncthreads();
        if (t == 0) g_idx64 = (any_nonzero == 0);
    }
}

// ---------------------------------------------------------------------------
// Kernel 2: fused TF32x3 tensor GEMM (xw = x @ W) + row histogram.
// 64-row tile, 103 KB smem -> 2 CTAs/SM (16 warps) so staging/hist of one
// CTA overlaps MMA of the other. 8 warps = 4(m) x 2(n); each warp: 16 rows
// x 32 cols = 4 n-tiles of m16n8k8, 3 mma per tile (hi*hi + hi*lo + lo*hi).
// ---------------------------------------------------------------------------
__global__ __launch_bounds__(256) void gemm_hist_kernel(
    const float* __restrict__ x, const float* __restrict__ W,
    float* __restrict__ xw,
    const void* __restrict__ adj_row,
    int n_nodes, int n_edges)
{
    extern __shared__ __align__(16) float smem[];
    float* Whi = smem;                                   // [128][68]
    float* Wlo = smem + F_IN * WS_STRIDE;                // [128][68]
    float* xs  = smem + 2 * F_IN * WS_STRIDE;            // [64][132]

    const int tid  = threadIdx.x;
    const int row0 = blockIdx.x * ROWS_PER_BLOCK;

    // Stage W -> tf32 hi / residual lo.
    for (int i = tid; i < F_IN * F_OUT; i += 256) {
        int k = i >> 6, n = i & 63;
        float w = W[i];
        float whi = __uint_as_float(f2tf32(w));
        Whi[k * WS_STRIDE + n] = whi;
        Wlo[k * WS_STRIDE + n] = w - whi;
    }

    // Stage x tile (coalesced float4; rows beyond n_nodes zeroed).
    for (int i = tid; i < ROWS_PER_BLOCK * F_IN / 4; i += 256) {
        int r = i / (F_IN / 4);
        int c = i % (F_IN / 4);
        int gr = row0 + r;
        float4 v = make_float4(0.f, 0.f, 0.f, 0.f);
        if (gr < n_nodes)
            v = ((const float4*)(x + (size_t)gr * F_IN))[c];
        ((float4*)(xs + r * XS_STRIDE))[c] = v;
    }

    // Histogram (independent work; RED is fire-and-forget, drains under MMA).
    {
        int stride = gridDim.x * 256;
        for (int e = blockIdx.x * 256 + tid; e < n_edges; e += stride) {
            int r = load_idx(adj_row, e);
            if ((unsigned)r < (unsigned)n_nodes)
                atomicAdd(&g_cnt[r], 1);
        }
    }
    __syncthreads();

    const int lane = tid & 31;
    const int warp = tid >> 5;
    const int grp  = lane >> 2;            // 0..7
    const int tc   = lane & 3;             // 0..3
    const int wrow = (warp & 3) * 16;      // m-tile: 4 warps cover 64 rows
    const int ncol0 = (warp >> 2) * 32;    // n-half: 2 warps cover 64 cols

    float acc[4][4];
    #pragma unroll
    for (int nt = 0; nt < 4; nt++)
        #pragma unroll
        for (int j = 0; j < 4; j++)
            acc[nt][j] = 0.f;

    #pragma unroll 4
    for (int ks = 0; ks < F_IN / 8; ks++) {
        int k0 = ks * 8;

        unsigned ahi[4], alo[4];
        {
            int rb = wrow + grp;
            float a0 = xs[(rb + 0) * XS_STRIDE + k0 + tc];
            float a1 = xs[(rb + 8) * XS_STRIDE + k0 + tc];
            float a2 = xs[(rb + 0) * XS_STRIDE + k0 + tc + 4];
            float a3 = xs[(rb + 8) * XS_STRIDE + k0 + tc + 4];
            ahi[0] = f2tf32(a0); alo[0] = f2tf32(a0 - __uint_as_float(ahi[0]));
            ahi[1] = f2tf32(a1); alo[1] = f2tf32(a1 - __uint_as_float(ahi[1]));
            ahi[2] = f2tf32(a2); alo[2] = f2tf32(a2 - __uint_as_float(ahi[2]));
            ahi[3] = f2tf32(a3); alo[3] = f2tf32(a3 - __uint_as_float(ahi[3]));
        }

        #pragma unroll
        for (int nt = 0; nt < 4; nt++) {
            int n = ncol0 + nt * 8 + grp;
            unsigned bh0 = __float_as_uint(Whi[(k0 + tc) * WS_STRIDE + n]);
            unsigned bh1 = __float_as_uint(Whi[(k0 + tc + 4) * WS_STRIDE + n]);
            unsigned bl0 = f2tf32(Wlo[(k0 + tc) * WS_STRIDE + n]);
            unsigned bl1 = f2tf32(Wlo[(k0 + tc + 4) * WS_STRIDE + n]);
            mma_tf32(acc[nt], ahi, bh0, bh1);
            mma_tf32(acc[nt], ahi, bl0, bl1);
            mma_tf32(acc[nt], alo, bh0, bh1);
        }
    }

    // Epilogue: c0/c1 at (grp, 2tc/2tc+1); c2/c3 at (grp+8, same cols).
    int r_lo = row0 + wrow + grp;
    int r_hi = r_lo + 8;
    #pragma unroll
    for (int nt = 0; nt < 4; nt++) {
        int col = ncol0 + nt * 8 + tc * 2;
        if (r_lo < n_nodes)
            *(float2*)(xw + (size_t)r_lo * F_OUT + col) =
                make_float2(acc[nt][0], acc[nt][1]);
        if (r_hi < n_nodes)
            *(float2*)(xw + (size_t)r_hi * F_OUT + col) =
                make_float2(acc[nt][2], acc[nt][3]);
    }
}

// ---------------------------------------------------------------------------
// CSR scan (per-chunk) and fused top-scan + finalize.
// ---------------------------------------------------------------------------
__global__ __launch_bounds__(SCAN_CHUNK) void scan_part_kernel(int n)
{
    __shared__ int s[SCAN_CHUNK];
    int t = threadIdx.x;
    int i = blockIdx.x * SCAN_CHUNK + t;
    int v = (i < n) ? g_cnt[i] : 0;
    s[t] = v;
    __syncthreads();
    #pragma unroll
    for (int off = 1; off < SCAN_CHUNK; off <<= 1) {
        int add = (t >= off) ? s[t - off] : 0;
        __syncthreads();
        s[t] += add;
        __syncthreads();
    }
    if (i < n) g_incl[i] = s[t];
    if (t == SCAN_CHUNK - 1) g_blocktot[blockIdx.x] = s[t];
}

// Each block redundantly inclusive-scans the <=128 chunk totals in smem,
// then finalizes its slice: row_ptr[i+1], cursor[i].
__global__ __launch_bounds__(256) void finalize_kernel(int n, int nchunks)
{
    __shared__ int s[SCAN_MAXBLK];
    int t = threadIdx.x;
    if (t < SCAN_MAXBLK)
        s[t] = (t < nchunks) ? g_blocktot[t] : 0;
    __syncthreads();
    #pragma unroll
    for (int off = 1; off < SCAN_MAXBLK; off <<= 1) {
        int add = 0;
        if (t < SCAN_MAXBLK && t >= off) add = s[t - off];
        __syncthreads();
        if (t < SCAN_MAXBLK) s[t] += add;
        __syncthreads();
    }
    int i = blockIdx.x * blockDim.x + t;
    if (i >= n) return;
    int chunk = i / SCAN_CHUNK;
    int excl = (chunk == 0) ? 0 : s[chunk - 1];
    int inc = g_incl[i] + excl;
    g_row_ptr[i + 1] = inc;
    g_cursor[i] = inc - g_cnt[i];
    if (i == 0) g_row_ptr[0] = 0;
}

__global__ void pack_kernel(const void* __restrict__ adj_row,
                            const void* __restrict__ adj_col,
                            const float* __restrict__ adj_val,
                            int n_edges, int n_nodes)
{
    int e = blockIdx.x * blockDim.x + threadIdx.x;
    if (e >= n_edges) return;
    int r = load_idx(adj_row, e);
    int c = load_idx(adj_col, e);
    if ((unsigned)r >= (unsigned)n_nodes || (unsigned)c >= (unsigned)n_nodes)
        return;
    float v = adj_val[e];
    int pos = atomicAdd(&g_cursor[r], 1);
    if (pos < E_CAP)
        g_packed[pos] = ((long long)__float_as_int(v) << 32) | (unsigned)c;
}

// ---------------------------------------------------------------------------
// Aggregate (pull): 16-lane half-warp per row; bias fused; no atomics.
// ---------------------------------------------------------------------------
__global__ __launch_bounds__(256) void aggregate_kernel(
    const float* __restrict__ xw, const float* __restrict__ b,
    float* __restrict__ out, int n_nodes)
{
    int g  = blockIdx.x * blockDim.x + threadIdx.x;
    int r  = g >> 4;
    int c4 = g & 15;
    if (r >= n_nodes) return;

    int i   = g_row_ptr[r];
    int end = g_row_ptr[r + 1];

    float4 acc = ((const float4*)b)[c4];
    const float4* xw4 = (const float4*)xw;

    for (; i + 4 <= end; i += 4) {
        long long p0 = g_packed[i + 0];
        long long p1 = g_packed[i + 1];
        long long p2 = g_packed[i + 2];
        long long p3 = g_packed[i + 3];
        int   c0 = (int)p0;  float v0 = __int_as_float((int)(p0 >> 32));
        int   c1 = (int)p1;  float v1 = __int_as_float((int)(p1 >> 32));
        int   c2 = (int)p2;  float v2 = __int_as_float((int)(p2 >> 32));
        int   c3 = (int)p3;  float v3 = __int_as_float((int)(p3 >> 32));
        float4 m0 = xw4[(size_t)c0 * 16 + c4];
        float4 m1 = xw4[(size_t)c1 * 16 + c4];
        float4 m2 = xw4[(size_t)c2 * 16 + c4];
        float4 m3 = xw4[(size_t)c3 * 16 + c4];
        acc.x += v0 * m0.x + v1 * m1.x + v2 * m2.x + v3 * m3.x;
        acc.y += v0 * m0.y + v1 * m1.y + v2 * m2.y + v3 * m3.y;
        acc.z += v0 * m0.z + v1 * m1.z + v2 * m2.z + v3 * m3.z;
        acc.w += v0 * m0.w + v1 * m1.w + v2 * m2.w + v3 * m3.w;
    }
    for (; i < end; i++) {
        long long p = g_packed[i];
        int   c = (int)p;
        float v = __int_as_float((int)(p >> 32));
        float4 m = xw4[(size_t)c * 16 + c4];
        acc.x += v * m.x;  acc.y += v * m.y;
        acc.z += v * m.z;  acc.w += v * m.w;
    }

    ((float4*)out)[(size_t)r * 16 + c4] = acc;
}

// ---------------------------------------------------------------------------
// Launch. Inputs (metadata order): x, adj_row, adj_col, adj_val, W, b
// ---------------------------------------------------------------------------
extern "C" void kernel_launch(void* const* d_in, const int* in_sizes, int n_in,
                              void* d_out, int out_size)
{
    const float* x       = (const float*)d_in[0];
    const void*  adj_row = d_in[1];
    const void*  adj_col = d_in[2];
    const float* adj_val = (const float*)d_in[3];
    const float* W       = (const float*)d_in[4];
    const float* b       = (const float*)d_in[5];
    float*       out     = (float*)d_out;

    const int n_nodes = in_sizes[0] / F_IN;
    const int n_edges = in_sizes[3];

    float* xw;
    cudaGetSymbolAddress((void**)&xw, g_xw);

    cudaFuncSetAttribute(gemm_hist_kernel,
                         cudaFuncAttributeMaxDynamicSharedMemorySize,
                         GEMM_SMEM_BYTES);

    const int EB = (n_edges + 255) / 256;
    const int NB = (n_nodes + 255) / 256;
    const int SCANB = (n_nodes + SCAN_CHUNK - 1) / SCAN_CHUNK;
    const int GB = (n_nodes + ROWS_PER_BLOCK - 1) / ROWS_PER_BLOCK;

    // 1) zero counters + index dtype detect
    prep_kernel<<<NB, 256>>>((const int*)adj_row, n_edges, n_nodes);

    // 2) fused tensor GEMM + histogram (2 CTAs/SM)
    gemm_hist_kernel<<<GB, 256, GEMM_SMEM_BYTES>>>(x, W, xw, adj_row,
                                                   n_nodes, n_edges);

    // 3) CSR scan + fused finalize, then pack
    scan_part_kernel<<<SCANB, SCAN_CHUNK>>>(n_nodes);
    finalize_kernel<<<NB, 256>>>(n_nodes, SCANB);
    pack_kernel<<<EB, 256>>>(adj_row, adj_col, adj_val, n_edges, n_nodes);

    // 4) pull-based aggregate (bias fused)
    aggregate_kernel<<<(n_nodes * 16 + 255) / 256, 256>>>(xw, b, out, n_nodes);
}

// round 13
// speedup vs baseline: 1.0566x; 1.0566x over previous
#include <cuda_runtime.h>
#include <cstdint>

// Shapes fixed by the reference:
//   x: [N, 128] f32, adj_row/adj_col: [E] int32-or-int64 (runtime detect),
//   adj_val: [E] f32, W: [128, 64] f32, b: [64] f32 -> out: [N, 64] f32
#define MAX_NODES 131072
#define E_CAP     1700000
#define F_IN  128
#define F_OUT 64
#define SCAN_CHUNK 1024
#define SCAN_MAXBLK 128

// ---- static device scratch (no cudaMalloc; no host-side static CUDA calls) ----
__device__ __align__(16) float g_xw[(size_t)MAX_NODES * F_OUT];
__device__ long long g_packed[E_CAP];      // lo32=col, hi32=val bits
__device__ int g_cnt[MAX_NODES];
__device__ int g_incl[MAX_NODES];
__device__ int g_blocktot[SCAN_MAXBLK];
__device__ int g_row_ptr[MAX_NODES + 1];
__device__ int g_cursor[MAX_NODES];
__device__ int g_idx64;

__device__ __forceinline__ int load_idx(const void* p, int e)
{
    return g_idx64 ? (int)((const long long*)p)[e] : ((const int*)p)[e];
}

// ---------------------------------------------------------------------------
// prep: zero g_cnt + index-dtype detect (block 0). int64 indices (<2^31)
// have every odd 32-bit word zero; int32 data has random ids there.
// ---------------------------------------------------------------------------
__global__ __launch_bounds__(256) void prep_kernel(
    const int* __restrict__ row_raw, int n_edges, int n_nodes)
{
    int i = blockIdx.x * blockDim.x + threadIdx.x;
    if (i < n_nodes) g_cnt[i] = 0;

    if (blockIdx.x == 0) {
        __shared__ int any_nonzero;
        int t = threadIdx.x;
        if (t == 0) any_nonzero = 0;
        __syncthreads();
        int limit = n_edges < 64 ? n_edges : 64;
        if (t < limit && row_raw[2 * t + 1] != 0)
            atomicOr(&any_nonzero, 1);
        __syncthreads();
        if (t == 0) g_idx64 = (any_nonzero == 0);
    }
}

// ---------------------------------------------------------------------------
// Fused FFMA GEMM (xw = x @ W) + row histogram.
// GEMM: block 256, tile 64x64, each thread 4 rows x 4 cols; 64 KB dyn smem.
// Hist: grid-stride LDG + RED.add prologue — fire-and-forget traffic that
// drains under the ~57us FFMA-bound compute phase (proven pattern from R8;
// the R8 slowdown was the tf32 path, not the fusion).
// ---------------------------------------------------------------------------
__global__ __launch_bounds__(256) void gemm_hist_kernel(
    const float* __restrict__ x, const float* __restrict__ W,
    float* __restrict__ xw, const void* __restrict__ adj_row,
    int n_nodes, int n_edges)
{
    extern __shared__ __align__(16) unsigned char smem_raw[];
    float4* Ws4 = (float4*)smem_raw;                         // 32 KB, [k][c4]
    float (*xs)[F_IN] = (float (*)[F_IN])(smem_raw + 32768); // 32 KB

    const int tid = threadIdx.x;
    const int row0 = blockIdx.x * 64;

    const float4* W4 = (const float4*)W;
    for (int i = tid; i < F_IN * F_OUT / 4; i += 256)
        Ws4[i] = W4[i];

    for (int i = tid; i < 64 * F_IN / 4; i += 256) {
        int r = i / (F_IN / 4);
        int c = i % (F_IN / 4);
        int gr = row0 + r;
        float4 v = make_float4(0.f, 0.f, 0.f, 0.f);
        if (gr < n_nodes)
            v = ((const float4*)(x + (size_t)gr * F_IN))[c];
        ((float4*)&xs[r][0])[c] = v;
    }

    // Histogram slice (independent of GEMM data; overlaps the FFMA phase).
    {
        int stride = gridDim.x * 256;
        for (int e = blockIdx.x * 256 + tid; e < n_edges; e += stride) {
            int r = load_idx(adj_row, e);
            if ((unsigned)r < (unsigned)n_nodes)
                atomicAdd(&g_cnt[r], 1);
        }
    }
    __syncthreads();

    const int c4 = tid & 15;
    const int r0 = (tid >> 4) * 4;

    float4 acc0 = make_float4(0.f, 0.f, 0.f, 0.f);
    float4 acc1 = acc0, acc2 = acc0, acc3 = acc0;

    #pragma unroll 4
    for (int k = 0; k < F_IN; k++) {
        float4 w = Ws4[k * 16 + c4];
        float a0 = xs[r0 + 0][k];
        float a1 = xs[r0 + 1][k];
        float a2 = xs[r0 + 2][k];
        float a3 = xs[r0 + 3][k];
        acc0.x += a0 * w.x; acc0.y += a0 * w.y; acc0.z += a0 * w.z; acc0.w += a0 * w.w;
        acc1.x += a1 * w.x; acc1.y += a1 * w.y; acc1.z += a1 * w.z; acc1.w += a1 * w.w;
        acc2.x += a2 * w.x; acc2.y += a2 * w.y; acc2.z += a2 * w.z; acc2.w += a2 * w.w;
        acc3.x += a3 * w.x; acc3.y += a3 * w.y; acc3.z += a3 * w.z; acc3.w += a3 * w.w;
    }

    int gr = row0 + r0;
    if (gr + 0 < n_nodes) ((float4*)(xw + (size_t)(gr + 0) * F_OUT))[c4] = acc0;
    if (gr + 1 < n_nodes) ((float4*)(xw + (size_t)(gr + 1) * F_OUT))[c4] = acc1;
    if (gr + 2 < n_nodes) ((float4*)(xw + (size_t)(gr + 2) * F_OUT))[c4] = acc2;
    if (gr + 3 < n_nodes) ((float4*)(xw + (size_t)(gr + 3) * F_OUT))[c4] = acc3;
}

// ---------------------------------------------------------------------------
// CSR scan (per-chunk inclusive) + fused top-scan/finalize.
// ---------------------------------------------------------------------------
__global__ __launch_bounds__(SCAN_CHUNK) void scan_part_kernel(int n)
{
    __shared__ int s[SCAN_CHUNK];
    int t = threadIdx.x;
    int i = blockIdx.x * SCAN_CHUNK + t;
    int v = (i < n) ? g_cnt[i] : 0;
    s[t] = v;
    __syncthreads();
    #pragma unroll
    for (int off = 1; off < SCAN_CHUNK; off <<= 1) {
        int add = (t >= off) ? s[t - off] : 0;
        __syncthreads();
        s[t] += add;
        __syncthreads();
    }
    if (i < n) g_incl[i] = s[t];
    if (t == SCAN_CHUNK - 1) g_blocktot[blockIdx.x] = s[t];
}

__global__ __launch_bounds__(256) void finalize_kernel(int n, int nchunks)
{
    __shared__ int s[SCAN_MAXBLK];
    int t = threadIdx.x;
    if (t < SCAN_MAXBLK)
        s[t] = (t < nchunks) ? g_blocktot[t] : 0;
    __syncthreads();
    #pragma unroll
    for (int off = 1; off < SCAN_MAXBLK; off <<= 1) {
        int add = 0;
        if (t < SCAN_MAXBLK && t >= off) add = s[t - off];
        __syncthreads();
        if (t < SCAN_MAXBLK) s[t] += add;
        __syncthreads();
    }
    int i = blockIdx.x * blockDim.x + t;
    if (i >= n) return;
    int chunk = i / SCAN_CHUNK;
    int excl = (chunk == 0) ? 0 : s[chunk - 1];
    int inc = g_incl[i] + excl;
    g_row_ptr[i + 1] = inc;
    g_cursor[i] = inc - g_cnt[i];
    if (i == 0) g_row_ptr[0] = 0;
}

__global__ void pack_kernel(const void* __restrict__ adj_row,
                            const void* __restrict__ adj_col,
                            const float* __restrict__ adj_val,
                            int n_edges, int n_nodes)
{
    int e = blockIdx.x * blockDim.x + threadIdx.x;
    if (e >= n_edges) return;
    int r = load_idx(adj_row, e);
    int c = load_idx(adj_col, e);
    if ((unsigned)r >= (unsigned)n_nodes || (unsigned)c >= (unsigned)n_nodes)
        return;
    float v = adj_val[e];
    int pos = atomicAdd(&g_cursor[r], 1);
    if (pos < E_CAP)
        g_packed[pos] = ((long long)__float_as_int(v) << 32) | (unsigned)c;
}

// ---------------------------------------------------------------------------
// Aggregate (pull): 16-lane half-warp per row; bias fused; no atomics.
// ---------------------------------------------------------------------------
__global__ __launch_bounds__(256) void aggregate_kernel(
    const float* __restrict__ xw, const float* __restrict__ b,
    float* __restrict__ out, int n_nodes)
{
    int g  = blockIdx.x * blockDim.x + threadIdx.x;
    int r  = g >> 4;
    int c4 = g & 15;
    if (r >= n_nodes) return;

    int i   = g_row_ptr[r];
    int end = g_row_ptr[r + 1];

    float4 acc = ((const float4*)b)[c4];
    const float4* xw4 = (const float4*)xw;

    for (; i + 4 <= end; i += 4) {
        long long p0 = g_packed[i + 0];
        long long p1 = g_packed[i + 1];
        long long p2 = g_packed[i + 2];
        long long p3 = g_packed[i + 3];
        int   c0 = (int)p0;  float v0 = __int_as_float((int)(p0 >> 32));
        int   c1 = (int)p1;  float v1 = __int_as_float((int)(p1 >> 32));
        int   c2 = (int)p2;  float v2 = __int_as_float((int)(p2 >> 32));
        int   c3 = (int)p3;  float v3 = __int_as_float((int)(p3 >> 32));
        float4 m0 = xw4[(size_t)c0 * 16 + c4];
        float4 m1 = xw4[(size_t)c1 * 16 + c4];
        float4 m2 = xw4[(size_t)c2 * 16 + c4];
        float4 m3 = xw4[(size_t)c3 * 16 + c4];
        acc.x += v0 * m0.x + v1 * m1.x + v2 * m2.x + v3 * m3.x;
        acc.y += v0 * m0.y + v1 * m1.y + v2 * m2.y + v3 * m3.y;
        acc.z += v0 * m0.z + v1 * m1.z + v2 * m2.z + v3 * m3.z;
        acc.w += v0 * m0.w + v1 * m1.w + v2 * m2.w + v3 * m3.w;
    }
    for (; i < end; i++) {
        long long p = g_packed[i];
        int   c = (int)p;
        float v = __int_as_float((int)(p >> 32));
        float4 m = xw4[(size_t)c * 16 + c4];
        acc.x += v * m.x;  acc.y += v * m.y;
        acc.z += v * m.z;  acc.w += v * m.w;
    }

    ((float4*)out)[(size_t)r * 16 + c4] = acc;
}

// ---------------------------------------------------------------------------
// Launch. Inputs (metadata order): x, adj_row, adj_col, adj_val, W, b
// Single stream; hist hidden inside the GEMM launch.
// ---------------------------------------------------------------------------
extern "C" void kernel_launch(void* const* d_in, const int* in_sizes, int n_in,
                              void* d_out, int out_size)
{
    const float* x       = (const float*)d_in[0];
    const void*  adj_row = d_in[1];
    const void*  adj_col = d_in[2];
    const float* adj_val = (const float*)d_in[3];
    const float* W       = (const float*)d_in[4];
    const float* b       = (const float*)d_in[5];
    float*       out     = (float*)d_out;

    const int n_nodes = in_sizes[0] / F_IN;
    const int n_edges = in_sizes[3];

    float* xw;
    cudaGetSymbolAddress((void**)&xw, g_xw);

    const int GEMM_SMEM = 65536;
    cudaFuncSetAttribute(gemm_hist_kernel,
                         cudaFuncAttributeMaxDynamicSharedMemorySize, GEMM_SMEM);

    const int EB = (n_edges + 255) / 256;
    const int NB = (n_nodes + 255) / 256;
    const int SCANB = (n_nodes + SCAN_CHUNK - 1) / SCAN_CHUNK;

    // 1) zero counters + index dtype detect
    prep_kernel<<<NB, 256>>>((const int*)adj_row, n_edges, n_nodes);

    // 2) fused FFMA GEMM + histogram
    gemm_hist_kernel<<<(n_nodes + 63) / 64, 256, GEMM_SMEM>>>(
        x, W, xw, adj_row, n_nodes, n_edges);

    // 3) CSR scan + fused finalize, then pack
    scan_part_kernel<<<SCANB, SCAN_CHUNK>>>(n_nodes);
    finalize_kernel<<<NB, 256>>>(n_nodes, SCANB);
    pack_kernel<<<EB, 256>>>(adj_row, adj_col, adj_val, n_edges, n_nodes);

    // 4) pull-based aggregate (bias fused)
    aggregate_kernel<<<(n_nodes * 16 + 255) / 256, 256>>>(xw, b, out, n_nodes);
}

// round 15
// speedup vs baseline: 1.1363x; 1.0755x over previous
#include <cuda_runtime.h>
#include <cuda_fp16.h>
#include <cstdint>

// Shapes fixed by the reference:
//   x: [N, 128] f32, adj_row/adj_col: [E] int32-or-int64 (runtime detect),
//   adj_val: [E] f32, W: [128, 64] f32, b: [64] f32 -> out: [N, 64] f32
#define MAX_NODES 131072
#define E_CAP     1700000
#define F_IN  128
#define F_OUT 64
#define SCAN_CHUNK 1024
#define SCAN_MAXBLK 128

// ---- static device scratch (no cudaMalloc; no host-side static CUDA calls) ----
__device__ __align__(16) __half g_xwh[(size_t)MAX_NODES * F_OUT];  // fp16 xw
__device__ long long g_packed[E_CAP];      // lo32=col, hi32=val bits
__device__ int g_cnt[MAX_NODES];
__device__ int g_incl[MAX_NODES];
__device__ int g_blocktot[SCAN_MAXBLK];
__device__ int g_row_ptr[MAX_NODES + 1];
__device__ int g_cursor[MAX_NODES];
__device__ int g_idx64;

__device__ __forceinline__ int load_idx(const void* p, int e)
{
    return g_idx64 ? (int)((const long long*)p)[e] : ((const int*)p)[e];
}

// ---------------------------------------------------------------------------
// prep: zero g_cnt + index-dtype detect (block 0). int64 indices (<2^31)
// have every odd 32-bit word zero; int32 data has random ids there.
// ---------------------------------------------------------------------------
__global__ __launch_bounds__(256) void prep_kernel(
    const int* __restrict__ row_raw, int n_edges, int n_nodes)
{
    int i = blockIdx.x * blockDim.x + threadIdx.x;
    if (i < n_nodes) g_cnt[i] = 0;

    if (blockIdx.x == 0) {
        __shared__ int any_nonzero;
        int t = threadIdx.x;
        if (t == 0) any_nonzero = 0;
        __syncthreads();
        int limit = n_edges < 64 ? n_edges : 64;
        if (t < limit && row_raw[2 * t + 1] != 0)
            atomicOr(&any_nonzero, 1);
        __syncthreads();
        if (t == 0) g_idx64 = (any_nonzero == 0);
    }
}

// ---------------------------------------------------------------------------
// Fused FFMA GEMM (xw = x @ W -> fp16) + row histogram.
// GEMM: block 256, tile 64x64, each thread 4 rows x 4 cols; 64 KB dyn smem.
// Hist: int4-vectorized (int32 path) grid-stride RED.add prologue.
// ---------------------------------------------------------------------------
__global__ __launch_bounds__(256) void gemm_hist_kernel(
    const float* __restrict__ x, const float* __restrict__ W,
    __half* __restrict__ xwh, const void* __restrict__ adj_row,
    int n_nodes, int n_edges)
{
    extern __shared__ __align__(16) unsigned char smem_raw[];
    float4* Ws4 = (float4*)smem_raw;                         // 32 KB, [k][c4]
    float (*xs)[F_IN] = (float (*)[F_IN])(smem_raw + 32768); // 32 KB

    const int tid = threadIdx.x;
    const int row0 = blockIdx.x * 64;

    const float4* W4 = (const float4*)W;
    for (int i = tid; i < F_IN * F_OUT / 4; i += 256)
        Ws4[i] = W4[i];

    for (int i = tid; i < 64 * F_IN / 4; i += 256) {
        int r = i / (F_IN / 4);
        int c = i % (F_IN / 4);
        int gr = row0 + r;
        float4 v = make_float4(0.f, 0.f, 0.f, 0.f);
        if (gr < n_nodes)
            v = ((const float4*)(x + (size_t)gr * F_IN))[c];
        ((float4*)&xs[r][0])[c] = v;
    }

    // Histogram slice (independent of GEMM; RED traffic drains under FFMA).
    {
        int stride = gridDim.x * 256;
        if (!g_idx64) {
            const int4* rr = (const int4*)adj_row;
            int nvec = n_edges >> 2;
            for (int i = blockIdx.x * 256 + tid; i < nvec; i += stride) {
                int4 v = rr[i];
                if ((unsigned)v.x < (unsigned)n_nodes) atomicAdd(&g_cnt[v.x], 1);
                if ((unsigned)v.y < (unsigned)n_nodes) atomicAdd(&g_cnt[v.y], 1);
                if ((unsigned)v.z < (unsigned)n_nodes) atomicAdd(&g_cnt[v.z], 1);
                if ((unsigned)v.w < (unsigned)n_nodes) atomicAdd(&g_cnt[v.w], 1);
            }
            if (blockIdx.x == 0) {   // tail
                for (int e = (nvec << 2) + tid; e < n_edges; e += 256) {
                    int r = ((const int*)adj_row)[e];
                    if ((unsigned)r < (unsigned)n_nodes) atomicAdd(&g_cnt[r], 1);
                }
            }
        } else {
            for (int e = blockIdx.x * 256 + tid; e < n_edges; e += stride) {
                int r = (int)((const long long*)adj_row)[e];
                if ((unsigned)r < (unsigned)n_nodes) atomicAdd(&g_cnt[r], 1);
            }
        }
    }
    __syncthreads();

    const int c4 = tid & 15;
    const int r0 = (tid >> 4) * 4;

    float4 acc0 = make_float4(0.f, 0.f, 0.f, 0.f);
    float4 acc1 = acc0, acc2 = acc0, acc3 = acc0;

    #pragma unroll 4
    for (int k = 0; k < F_IN; k++) {
        float4 w = Ws4[k * 16 + c4];
        float a0 = xs[r0 + 0][k];
        float a1 = xs[r0 + 1][k];
        float a2 = xs[r0 + 2][k];
        float a3 = xs[r0 + 3][k];
        acc0.x += a0 * w.x; acc0.y += a0 * w.y; acc0.z += a0 * w.z; acc0.w += a0 * w.w;
        acc1.x += a1 * w.x; acc1.y += a1 * w.y; acc1.z += a1 * w.z; acc1.w += a1 * w.w;
        acc2.x += a2 * w.x; acc2.y += a2 * w.y; acc2.z += a2 * w.z; acc2.w += a2 * w.w;
        acc3.x += a3 * w.x; acc3.y += a3 * w.y; acc3.z += a3 * w.z; acc3.w += a3 * w.w;
    }

    // Epilogue: round once to fp16, store 8B per row-slice.
    int gr = row0 + r0;
    #pragma unroll
    for (int q = 0; q < 4; q++) {
        float4 a = (q == 0) ? acc0 : (q == 1) ? acc1 : (q == 2) ? acc2 : acc3;
        if (gr + q < n_nodes) {
            __half2 h01 = __float22half2_rn(make_float2(a.x, a.y));
            __half2 h23 = __float22half2_rn(make_float2(a.z, a.w));
            uint2 u;
            u.x = *(unsigned*)&h01;
            u.y = *(unsigned*)&h23;
            ((uint2*)(xwh + (size_t)(gr + q) * F_OUT))[c4] = u;
        }
    }
}

// ---------------------------------------------------------------------------
// CSR scan (per-chunk inclusive) + fused top-scan/finalize.
// ---------------------------------------------------------------------------
__global__ __launch_bounds__(SCAN_CHUNK) void scan_part_kernel(int n)
{
    __shared__ int s[SCAN_CHUNK];
    int t = threadIdx.x;
    int i = blockIdx.x * SCAN_CHUNK + t;
    int v = (i < n) ? g_cnt[i] : 0;
    s[t] = v;
    __syncthreads();
    #pragma unroll
    for (int off = 1; off < SCAN_CHUNK; off <<= 1) {
        int add = (t >= off) ? s[t - off] : 0;
        __syncthreads();
        s[t] += add;
        __syncthreads();
    }
    if (i < n) g_incl[i] = s[t];
    if (t == SCAN_CHUNK - 1) g_blocktot[blockIdx.x] = s[t];
}

__global__ __launch_bounds__(256) void finalize_kernel(int n, int nchunks)
{
    __shared__ int s[SCAN_MAXBLK];
    int t = threadIdx.x;
    if (t < SCAN_MAXBLK)
        s[t] = (t < nchunks) ? g_blocktot[t] : 0;
    __syncthreads();
    #pragma unroll
    for (int off = 1; off < SCAN_MAXBLK; off <<= 1) {
        int add = 0;
        if (t < SCAN_MAXBLK && t >= off) add = s[t - off];
        __syncthreads();
        if (t < SCAN_MAXBLK) s[t] += add;
        __syncthreads();
    }
    int i = blockIdx.x * blockDim.x + t;
    if (i >= n) return;
    int chunk = i / SCAN_CHUNK;
    int excl = (chunk == 0) ? 0 : s[chunk - 1];
    int inc = g_incl[i] + excl;
    g_row_ptr[i + 1] = inc;
    g_cursor[i] = inc - g_cnt[i];
    if (i == 0) g_row_ptr[0] = 0;
}

// ---------------------------------------------------------------------------
// pack: 4 edges per thread, vectorized loads (int32 path) -> MLP up front.
// ---------------------------------------------------------------------------
__global__ __launch_bounds__(256) void pack_kernel(
    const void* __restrict__ adj_row, const void* __restrict__ adj_col,
    const float* __restrict__ adj_val, int n_edges, int n_nodes)
{
    int t = blockIdx.x * blockDim.x + threadIdx.x;

    if (!g_idx64) {
        int nvec = n_edges >> 2;
        if (t < nvec) {
            int4   r4 = ((const int4*)adj_row)[t];
            int4   c4 = ((const int4*)adj_col)[t];
            float4 v4 = ((const float4*)adj_val)[t];
            int    rs[4] = { r4.x, r4.y, r4.z, r4.w };
            int    cs[4] = { c4.x, c4.y, c4.z, c4.w };
            float  vs[4] = { v4.x, v4.y, v4.z, v4.w };
            #pragma unroll
            for (int q = 0; q < 4; q++) {
                if ((unsigned)rs[q] >= (unsigned)n_nodes ||
                    (unsigned)cs[q] >= (unsigned)n_nodes) continue;
                int pos = atomicAdd(&g_cursor[rs[q]], 1);
                if (pos < E_CAP)
                    g_packed[pos] = ((long long)__float_as_int(vs[q]) << 32)
                                  | (unsigned)cs[q];
            }
        } else {
            // tail edges
            int e = (nvec << 2) + (t - nvec);
            if (e < n_edges) {
                int r = ((const int*)adj_row)[e];
                int c = ((const int*)adj_col)[e];
                if ((unsigned)r < (unsigned)n_nodes &&
                    (unsigned)c < (unsigned)n_nodes) {
                    int pos = atomicAdd(&g_cursor[r], 1);
                    if (pos < E_CAP)
                        g_packed[pos] =
                            ((long long)__float_as_int(adj_val[e]) << 32)
                            | (unsigned)c;
                }
            }
        }
    } else {
        for (int q = 0; q < 4; q++) {
            int e = t * 4 + q;
            if (e >= n_edges) break;
            int r = (int)((const long long*)adj_row)[e];
            int c = (int)((const long long*)adj_col)[e];
            if ((unsigned)r >= (unsigned)n_nodes ||
                (unsigned)c >= (unsigned)n_nodes) continue;
            int pos = atomicAdd(&g_cursor[r], 1);
            if (pos < E_CAP)
                g_packed[pos] = ((long long)__float_as_int(adj_val[e]) << 32)
                              | (unsigned)c;
        }
    }
}

// ---------------------------------------------------------------------------
// Aggregate (pull, fp16 gather): 16-lane half-warp per row; each lane owns
// 4 cols (8B of fp16); fp32 accumulate; bias fused; no atomics.
// ---------------------------------------------------------------------------
__global__ __launch_bounds__(256) void aggregate_kernel(
    const __half* __restrict__ xwh, const float* __restrict__ b,
    float* __restrict__ out, int n_nodes)
{
    int g  = blockIdx.x * blockDim.x + threadIdx.x;
    int r  = g >> 4;
    int c4 = g & 15;
    if (r >= n_nodes) return;

    int i   = g_row_ptr[r];
    int end = g_row_ptr[r + 1];

    float4 acc = ((const float4*)b)[c4];
    const uint2* x2 = (const uint2*)xwh;   // row = 16 uint2 (64 halves)

    for (; i + 4 <= end; i += 4) {
        long long p0 = g_packed[i + 0];
        long long p1 = g_packed[i + 1];
        long long p2 = g_packed[i + 2];
        long long p3 = g_packed[i + 3];
        int   c0 = (int)p0;  float v0 = __int_as_float((int)(p0 >> 32));
        int   c1 = (int)p1;  float v1 = __int_as_float((int)(p1 >> 32));
        int   c2 = (int)p2;  float v2 = __int_as_float((int)(p2 >> 32));
        int   c3 = (int)p3;  float v3 = __int_as_float((int)(p3 >> 32));
        uint2 m0 = x2[(size_t)c0 * 16 + c4];
        uint2 m1 = x2[(size_t)c1 * 16 + c4];
        uint2 m2 = x2[(size_t)c2 * 16 + c4];
        uint2 m3 = x2[(size_t)c3 * 16 + c4];
        float2 a0 = __half22float2(*(__half2*)&m0.x);
        float2 b0 = __half22float2(*(__half2*)&m0.y);
        float2 a1 = __half22float2(*(__half2*)&m1.x);
        float2 b1 = __half22float2(*(__half2*)&m1.y);
        float2 a2 = __half22float2(*(__half2*)&m2.x);
        float2 b2 = __half22float2(*(__half2*)&m2.y);
        float2 a3 = __half22float2(*(__half2*)&m3.x);
        float2 b3 = __half22float2(*(__half2*)&m3.y);
        acc.x += v0 * a0.x + v1 * a1.x + v2 * a2.x + v3 * a3.x;
        acc.y += v0 * a0.y + v1 * a1.y + v2 * a2.y + v3 * a3.y;
        acc.z += v0 * b0.x + v1 * b1.x + v2 * b2.x + v3 * b3.x;
        acc.w += v0 * b0.y + v1 * b1.y + v2 * b2.y + v3 * b3.y;
    }
    for (; i < end; i++) {
        long long p = g_packed[i];
        int   c = (int)p;
        float v = __int_as_float((int)(p >> 32));
        uint2 m = x2[(size_t)c * 16 + c4];
        float2 a = __half22float2(*(__half2*)&m.x);
        float2 bb = __half22float2(*(__half2*)&m.y);
        acc.x += v * a.x;  acc.y += v * a.y;
        acc.z += v * bb.x; acc.w += v * bb.y;
    }

    ((float4*)out)[(size_t)r * 16 + c4] = acc;
}

// ---------------------------------------------------------------------------
// Launch. Inputs (metadata order): x, adj_row, adj_col, adj_val, W, b
// ---------------------------------------------------------------------------
extern "C" void kernel_launch(void* const* d_in, const int* in_sizes, int n_in,
                              void* d_out, int out_size)
{
    const float* x       = (const float*)d_in[0];
    const void*  adj_row = d_in[1];
    const void*  adj_col = d_in[2];
    const float* adj_val = (const float*)d_in[3];
    const float* W       = (const float*)d_in[4];
    const float* b       = (const float*)d_in[5];
    float*       out     = (float*)d_out;

    const int n_nodes = in_sizes[0] / F_IN;
    const int n_edges = in_sizes[3];

    __half* xwh;
    cudaGetSymbolAddress((void**)&xwh, g_xwh);

    const int GEMM_SMEM = 65536;
    cudaFuncSetAttribute(gemm_hist_kernel,
                         cudaFuncAttributeMaxDynamicSharedMemorySize, GEMM_SMEM);

    const int NB = (n_nodes + 255) / 256;
    const int SCANB = (n_nodes + SCAN_CHUNK - 1) / SCAN_CHUNK;
    // pack: nvec vector-threads + tail threads
    const int PT = (n_edges >> 2) + (n_edges & 3);
    const int PB = (PT + 255) / 256;

    // 1) zero counters + index dtype detect
    prep_kernel<<<NB, 256>>>((const int*)adj_row, n_edges, n_nodes);

    // 2) fused FFMA GEMM (fp16 out) + vectorized histogram
    gemm_hist_kernel<<<(n_nodes + 63) / 64, 256, GEMM_SMEM>>>(
        x, W, xwh, adj_row, n_nodes, n_edges);

    // 3) CSR scan + fused finalize, then batched pack
    scan_part_kernel<<<SCANB, SCAN_CHUNK>>>(n_nodes);
    finalize_kernel<<<NB, 256>>>(n_nodes, SCANB);
    pack_kernel<<<PB, 256>>>(adj_row, adj_col, adj_val, n_edges, n_nodes);

    // 4) pull-based aggregate (fp16 gather, fp32 accumulate, bias fused)
    aggregate_kernel<<<(n_nodes * 16 + 255) / 256, 256>>>(xwh, b, out, n_nodes);
}

// round 17
// speedup vs baseline: 1.4200x; 1.2496x over previous
#include <cuda_runtime.h>
#include <cuda_fp16.h>
#include <cstdint>

// Shapes fixed by the reference:
//   x: [N, 128] f32, adj_row/adj_col: [E] int32-or-int64 (runtime detect),
//   adj_val: [E] f32, W: [128, 64] f32, b: [64] f32 -> out: [N, 64] f32
#define MAX_NODES 131072
#define E_CAP     1700000
#define F_IN  128
#define F_OUT 64
#define SCAN_CHUNK 1024
#define SCAN_MAXBLK 128

// ---- fp16 mma GEMM tile config ----
#define GT_ROWS 128
#define HSTRIDE 136                       // halves per smem row (conflict-free)
#define AS_HALVES (GT_ROWS * HSTRIDE)     // 17408
#define BS_HALVES (F_OUT * HSTRIDE)       // 8704
#define GT_SMEM ((AS_HALVES + BS_HALVES) * 2)   // 52224 bytes

// ---- static device scratch (no cudaMalloc; no host-side static CUDA calls) ----
__device__ __align__(16) __half g_xwh[(size_t)MAX_NODES * F_OUT];  // fp16 xw
__device__ long long g_packed[E_CAP];      // lo32=col, hi32=val bits
__device__ int g_cnt[MAX_NODES];
__device__ int g_incl[MAX_NODES];
__device__ int g_blocktot[SCAN_MAXBLK];
__device__ int g_row_ptr[MAX_NODES + 1];
__device__ int g_cursor[MAX_NODES];
__device__ int g_idx64;

// ---------------------------------------------------------------------------
// prep: zero g_cnt + index-dtype detect (block 0). int64 indices (<2^31)
// have every odd 32-bit word zero; int32 data has random ids there.
// ---------------------------------------------------------------------------
__global__ __launch_bounds__(256) void prep_kernel(
    const int* __restrict__ row_raw, int n_edges, int n_nodes)
{
    int i = blockIdx.x * blockDim.x + threadIdx.x;
    if (i < n_nodes) g_cnt[i] = 0;

    if (blockIdx.x == 0) {
        __shared__ int any_nonzero;
        int t = threadIdx.x;
        if (t == 0) any_nonzero = 0;
        __syncthreads();
        int limit = n_edges < 64 ? n_edges : 64;
        if (t < limit && row_raw[2 * t + 1] != 0)
            atomicOr(&any_nonzero, 1);
        __syncthreads();
        if (t == 0) g_idx64 = (any_nonzero == 0);
    }
}

// m16n8k16 fp16 mma, fp32 accumulate (fragment maps validated by R8/R9 k8 runs)
__device__ __forceinline__ void mma16816(float* d, unsigned a0, unsigned a1,
                                         unsigned a2, unsigned a3,
                                         unsigned b0, unsigned b1)
{
    asm volatile(
        "mma.sync.aligned.m16n8k16.row.col.f32.f16.f16.f32 "
        "{%0,%1,%2,%3}, {%4,%5,%6,%7}, {%8,%9}, {%0,%1,%2,%3};"
        : "+f"(d[0]), "+f"(d[1]), "+f"(d[2]), "+f"(d[3])
        : "r"(a0), "r"(a1), "r"(a2), "r"(a3), "r"(b0), "r"(b1));
}

// ---------------------------------------------------------------------------
// Fused fp16-mma GEMM (xw = x @ W -> fp16) + row histogram.
// 128-row tile, 8 warps = 8 m16 tiles; each warp n=64 (8 n-tiles), k=128
// (8 k16 steps). x,W converted to fp16 ONCE at staging; fp32 accumulate.
// A frag: 4 LDS.32/ks; B frag: 2 LDS.32/nt (Bs = W^T as [n][k] row-major).
// Hist: int4-vectorized grid-stride RED.add prologue (drains under MMA).
// ---------------------------------------------------------------------------
__global__ __launch_bounds__(256) void gemm_hist_kernel(
    const float* __restrict__ x, const float* __restrict__ W,
    __half* __restrict__ xwh, const void* __restrict__ adj_row,
    int n_nodes, int n_edges)
{
    extern __shared__ __align__(16) __half hsm[];
    __half* As = hsm;                 // [128][136]
    __half* Bs = hsm + AS_HALVES;     // [64][136]  (Bs[n][k] = W[k][n])

    const int tid = threadIdx.x;
    const int row0 = blockIdx.x * GT_ROWS;

    // Stage W -> Bs (transpose to [n][k], fp16)
    for (int i = tid; i < F_IN * F_OUT; i += 256) {
        int k = i >> 6, n = i & 63;
        Bs[n * HSTRIDE + k] = __float2half(W[i]);
    }

    // Stage x tile -> As (fp16); tail rows zeroed
    for (int i = tid; i < GT_ROWS * (F_IN / 4); i += 256) {
        int r  = i >> 5;          // 32 float4 per row
        int c4 = i & 31;
        int gr = row0 + r;
        float4 v = make_float4(0.f, 0.f, 0.f, 0.f);
        if (gr < n_nodes)
            v = ((const float4*)(x + (size_t)gr * F_IN))[c4];
        __half2 h01 = __float22half2_rn(make_float2(v.x, v.y));
        __half2 h23 = __float22half2_rn(make_float2(v.z, v.w));
        uint2 u;
        u.x = *(unsigned*)&h01;
        u.y = *(unsigned*)&h23;
        *(uint2*)(As + r * HSTRIDE + c4 * 4) = u;
    }

    // Histogram slice (independent of GEMM; RED traffic drains under MMA).
    {
        int stride = gridDim.x * 256;
        if (!g_idx64) {
            const int4* rr = (const int4*)adj_row;
            int nvec = n_edges >> 2;
            for (int i = blockIdx.x * 256 + tid; i < nvec; i += stride) {
                int4 v = rr[i];
                if ((unsigned)v.x < (unsigned)n_nodes) atomicAdd(&g_cnt[v.x], 1);
                if ((unsigned)v.y < (unsigned)n_nodes) atomicAdd(&g_cnt[v.y], 1);
                if ((unsigned)v.z < (unsigned)n_nodes) atomicAdd(&g_cnt[v.z], 1);
                if ((unsigned)v.w < (unsigned)n_nodes) atomicAdd(&g_cnt[v.w], 1);
            }
            if (blockIdx.x == 0) {   // tail
                for (int e = (nvec << 2) + tid; e < n_edges; e += 256) {
                    int r = ((const int*)adj_row)[e];
                    if ((unsigned)r < (unsigned)n_nodes) atomicAdd(&g_cnt[r], 1);
                }
            }
        } else {
            for (int e = blockIdx.x * 256 + tid; e < n_edges; e += stride) {
                int r = (int)((const long long*)adj_row)[e];
                if ((unsigned)r < (unsigned)n_nodes) atomicAdd(&g_cnt[r], 1);
            }
        }
    }
    __syncthreads();

    const int lane = tid & 31;
    const int wm   = tid >> 5;        // warp -> m16 tile (8 tiles = 128 rows)
    const int g    = lane >> 2;       // 0..7
    const int t    = lane & 3;        // 0..3

    float acc[8][4];
    #pragma unroll
    for (int nt = 0; nt < 8; nt++)
        #pragma unroll
        for (int j = 0; j < 4; j++)
            acc[nt][j] = 0.f;

    const __half* Ar0 = As + (wm * 16 + g) * HSTRIDE;
    const __half* Ar8 = Ar0 + 8 * HSTRIDE;

    #pragma unroll
    for (int ks = 0; ks < 8; ks++) {
        int k0 = ks * 16 + 2 * t;
        unsigned a0 = *(const unsigned*)(Ar0 + k0);
        unsigned a1 = *(const unsigned*)(Ar8 + k0);
        unsigned a2 = *(const unsigned*)(Ar0 + k0 + 8);
        unsigned a3 = *(const unsigned*)(Ar8 + k0 + 8);
        #pragma unroll
        for (int nt = 0; nt < 8; nt++) {
            const __half* Bn = Bs + (nt * 8 + g) * HSTRIDE + k0;
            unsigned b0 = *(const unsigned*)(Bn);
            unsigned b1 = *(const unsigned*)(Bn + 8);
            mma16816(acc[nt], a0, a1, a2, a3, b0, b1);
        }
    }

    // Epilogue: c0/c1 = (row g, col 2t/2t+1), c2/c3 = (row g+8, same cols).
    int r_lo = row0 + wm * 16 + g;
    int r_hi = r_lo + 8;
    #pragma unroll
    for (int nt = 0; nt < 8; nt++) {
        int col = nt * 8 + 2 * t;
        if (r_lo < n_nodes) {
            __half2 h = __float22half2_rn(make_float2(acc[nt][0], acc[nt][1]));
            *(__half2*)(xwh + (size_t)r_lo * F_OUT + col) = h;
        }
        if (r_hi < n_nodes) {
            __half2 h = __float22half2_rn(make_float2(acc[nt][2], acc[nt][3]));
            *(__half2*)(xwh + (size_t)r_hi * F_OUT + col) = h;
        }
    }
}

// ---------------------------------------------------------------------------
// CSR scan (per-chunk inclusive) + fused top-scan/finalize.
// ---------------------------------------------------------------------------
__global__ __launch_bounds__(SCAN_CHUNK) void scan_part_kernel(int n)
{
    __shared__ int s[SCAN_CHUNK];
    int t = threadIdx.x;
    int i = blockIdx.x * SCAN_CHUNK + t;
    int v = (i < n) ? g_cnt[i] : 0;
    s[t] = v;
    __syncthreads();
    #pragma unroll
    for (int off = 1; off < SCAN_CHUNK; off <<= 1) {
        int add = (t >= off) ? s[t - off] : 0;
        __syncthreads();
        s[t] += add;
        __syncthreads();
    }
    if (i < n) g_incl[i] = s[t];
    if (t == SCAN_CHUNK - 1) g_blocktot[blockIdx.x] = s[t];
}

__global__ __launch_bounds__(256) void finalize_kernel(int n, int nchunks)
{
    __shared__ int s[SCAN_MAXBLK];
    int t = threadIdx.x;
    if (t < SCAN_MAXBLK)
        s[t] = (t < nchunks) ? g_blocktot[t] : 0;
    __syncthreads();
    #pragma unroll
    for (int off = 1; off < SCAN_MAXBLK; off <<= 1) {
        int add = 0;
        if (t < SCAN_MAXBLK && t >= off) add = s[t - off];
        __syncthreads();
        if (t < SCAN_MAXBLK) s[t] += add;
        __syncthreads();
    }
    int i = blockIdx.x * blockDim.x + t;
    if (i >= n) return;
    int chunk = i / SCAN_CHUNK;
    int excl = (chunk == 0) ? 0 : s[chunk - 1];
    int inc = g_incl[i] + excl;
    g_row_ptr[i + 1] = inc;
    g_cursor[i] = inc - g_cnt[i];
    if (i == 0) g_row_ptr[0] = 0;
}

// ---------------------------------------------------------------------------
// pack: 4 edges per thread, vectorized loads (int32 path) -> MLP up front.
// ---------------------------------------------------------------------------
__global__ __launch_bounds__(256) void pack_kernel(
    const void* __restrict__ adj_row, const void* __restrict__ adj_col,
    const float* __restrict__ adj_val, int n_edges, int n_nodes)
{
    int t = blockIdx.x * blockDim.x + threadIdx.x;

    if (!g_idx64) {
        int nvec = n_edges >> 2;
        if (t < nvec) {
            int4   r4 = ((const int4*)adj_row)[t];
            int4   c4 = ((const int4*)adj_col)[t];
            float4 v4 = ((const float4*)adj_val)[t];
            int    rs[4] = { r4.x, r4.y, r4.z, r4.w };
            int    cs[4] = { c4.x, c4.y, c4.z, c4.w };
            float  vs[4] = { v4.x, v4.y, v4.z, v4.w };
            #pragma unroll
            for (int q = 0; q < 4; q++) {
                if ((unsigned)rs[q] >= (unsigned)n_nodes ||
                    (unsigned)cs[q] >= (unsigned)n_nodes) continue;
                int pos = atomicAdd(&g_cursor[rs[q]], 1);
                if (pos < E_CAP)
                    g_packed[pos] = ((long long)__float_as_int(vs[q]) << 32)
                                  | (unsigned)cs[q];
            }
        } else {
            int e = (nvec << 2) + (t - nvec);
            if (e < n_edges) {
                int r = ((const int*)adj_row)[e];
                int c = ((const int*)adj_col)[e];
                if ((unsigned)r < (unsigned)n_nodes &&
                    (unsigned)c < (unsigned)n_nodes) {
                    int pos = atomicAdd(&g_cursor[r], 1);
                    if (pos < E_CAP)
                        g_packed[pos] =
                            ((long long)__float_as_int(adj_val[e]) << 32)
                            | (unsigned)c;
                }
            }
        }
    } else {
        for (int q = 0; q < 4; q++) {
            int e = t * 4 + q;
            if (e >= n_edges) break;
            int r = (int)((const long long*)adj_row)[e];
            int c = (int)((const long long*)adj_col)[e];
            if ((unsigned)r >= (unsigned)n_nodes ||
                (unsigned)c >= (unsigned)n_nodes) continue;
            int pos = atomicAdd(&g_cursor[r], 1);
            if (pos < E_CAP)
                g_packed[pos] = ((long long)__float_as_int(adj_val[e]) << 32)
                              | (unsigned)c;
        }
    }
}

// ---------------------------------------------------------------------------
// Aggregate (pull, fp16 gather): 16-lane half-warp per row; each lane owns
// 4 cols (8B of fp16); fp32 accumulate; bias fused; no atomics.
// ---------------------------------------------------------------------------
__global__ __launch_bounds__(256) void aggregate_kernel(
    const __half* __restrict__ xwh, const float* __restrict__ b,
    float* __restrict__ out, int n_nodes)
{
    int g  = blockIdx.x * blockDim.x + threadIdx.x;
    int r  = g >> 4;
    int c4 = g & 15;
    if (r >= n_nodes) return;

    int i   = g_row_ptr[r];
    int end = g_row_ptr[r + 1];

    float4 acc = ((const float4*)b)[c4];
    const uint2* x2 = (const uint2*)xwh;   // row = 16 uint2 (64 halves)

    for (; i + 4 <= end; i += 4) {
        long long p0 = g_packed[i + 0];
        long long p1 = g_packed[i + 1];
        long long p2 = g_packed[i + 2];
        long long p3 = g_packed[i + 3];
        int   c0 = (int)p0;  float v0 = __int_as_float((int)(p0 >> 32));
        int   c1 = (int)p1;  float v1 = __int_as_float((int)(p1 >> 32));
        int   c2 = (int)p2;  float v2 = __int_as_float((int)(p2 >> 32));
        int   c3 = (int)p3;  float v3 = __int_as_float((int)(p3 >> 32));
        uint2 m0 = x2[(size_t)c0 * 16 + c4];
        uint2 m1 = x2[(size_t)c1 * 16 + c4];
        uint2 m2 = x2[(size_t)c2 * 16 + c4];
        uint2 m3 = x2[(size_t)c3 * 16 + c4];
        float2 a0 = __half22float2(*(__half2*)&m0.x);
        float2 b0 = __half22float2(*(__half2*)&m0.y);
        float2 a1 = __half22float2(*(__half2*)&m1.x);
        float2 b1 = __half22float2(*(__half2*)&m1.y);
        float2 a2 = __half22float2(*(__half2*)&m2.x);
        float2 b2 = __half22float2(*(__half2*)&m2.y);
        float2 a3 = __half22float2(*(__half2*)&m3.x);
        float2 b3 = __half22float2(*(__half2*)&m3.y);
        acc.x += v0 * a0.x + v1 * a1.x + v2 * a2.x + v3 * a3.x;
        acc.y += v0 * a0.y + v1 * a1.y + v2 * a2.y + v3 * a3.y;
        acc.z += v0 * b0.x + v1 * b1.x + v2 * b2.x + v3 * b3.x;
        acc.w += v0 * b0.y + v1 * b1.y + v2 * b2.y + v3 * b3.y;
    }
    for (; i < end; i++) {
        long long p = g_packed[i];
        int   c = (int)p;
        float v = __int_as_float((int)(p >> 32));
        uint2 m = x2[(size_t)c * 16 + c4];
        float2 a = __half22float2(*(__half2*)&m.x);
        float2 bb = __half22float2(*(__half2*)&m.y);
        acc.x += v * a.x;  acc.y += v * a.y;
        acc.z += v * bb.x; acc.w += v * bb.y;
    }

    ((float4*)out)[(size_t)r * 16 + c4] = acc;
}

// ---------------------------------------------------------------------------
// Launch. Inputs (metadata order): x, adj_row, adj_col, adj_val, W, b
// ---------------------------------------------------------------------------
extern "C" void kernel_launch(void* const* d_in, const int* in_sizes, int n_in,
                              void* d_out, int out_size)
{
    const float* x       = (const float*)d_in[0];
    const void*  adj_row = d_in[1];
    const void*  adj_col = d_in[2];
    const float* adj_val = (const float*)d_in[3];
    const float* W       = (const float*)d_in[4];
    const float* b       = (const float*)d_in[5];
    float*       out     = (float*)d_out;

    const int n_nodes = in_sizes[0] / F_IN;
    const int n_edges = in_sizes[3];

    __half* xwh;
    cudaGetSymbolAddress((void**)&xwh, g_xwh);

    cudaFuncSetAttribute(gemm_hist_kernel,
                         cudaFuncAttributeMaxDynamicSharedMemorySize, GT_SMEM);

    const int NB = (n_nodes + 255) / 256;
    const int SCANB = (n_nodes + SCAN_CHUNK - 1) / SCAN_CHUNK;
    const int GB = (n_nodes + GT_ROWS - 1) / GT_ROWS;
    const int PT = (n_edges >> 2) + (n_edges & 3);
    const int PB = (PT + 255) / 256;

    // 1) zero counters + index dtype detect
    prep_kernel<<<NB, 256>>>((const int*)adj_row, n_edges, n_nodes);

    // 2) fused fp16-mma GEMM (fp16 out) + vectorized histogram
    gemm_hist_kernel<<<GB, 256, GT_SMEM>>>(x, W, xwh, adj_row,
                                           n_nodes, n_edges);

    // 3) CSR scan + fused finalize, then batched pack
    scan_part_kernel<<<SCANB, SCAN_CHUNK>>>(n_nodes);
    finalize_kernel<<<NB, 256>>>(n_nodes, SCANB);
    pack_kernel<<<PB, 256>>>(adj_row, adj_col, adj_val, n_edges, n_nodes);

    // 4) pull-based aggregate (fp16 gather, fp32 accumulate, bias fused)
    aggregate_kernel<<<(n_nodes * 16 + 255) / 256, 256>>>(xwh, b, out, n_nodes);
}